// round 1
// baseline (speedup 1.0000x reference)
#include <cuda_runtime.h>
#include <cstdint>

// ---------------------------------------------------------------------------
// QFCModel: analytic collapse of the 4-qubit circuit.
//
//   theta_i = mean of 6x6 pool block (row-block 0, col-block i) = mean of
//             pixels p in [0,144) with (p%24)/6 == i.
//   e_i     = cos(beta_i)*cos(theta_i) + sin(alpha_i)*sin(beta_i)*sin(theta_i)
//   out     = [e0, e0*e1, e0*e1*e2, e0*e1*e2*e3]
//   then BatchNorm1d (training mode, biased var, eps=1e-5).
// ---------------------------------------------------------------------------

#define BLK 256
#define MAX_NBLK 1024   // supports up to 262144 batch elements

__device__ double g_partial[8][MAX_NBLK];  // 4 sums + 4 sumsqs, per block
__device__ float  g_scale[4];
__device__ float  g_shift[4];

__global__ __launch_bounds__(BLK)
void k_circuit(const float* __restrict__ x,
               const float* __restrict__ params,
               float* __restrict__ raw)
{
    const int b = blockIdx.x * BLK + threadIdx.x;

    // Each image: 576 floats = 144 float4; we need the first 36 float4 (144 floats).
    const float4* xv = reinterpret_cast<const float4*>(x) + (size_t)b * 144;

    float s[4] = {0.f, 0.f, 0.f, 0.f};
    #pragma unroll
    for (int k = 0; k < 36; ++k) {
        float4 v = __ldg(xv + k);
        const int p = 4 * k;
        s[((p + 0) % 24) / 6] += v.x;   // indices are compile-time constants
        s[((p + 1) % 24) / 6] += v.y;
        s[((p + 2) % 24) / 6] += v.z;
        s[((p + 3) % 24) / 6] += v.w;
    }

    float e[4];
    #pragma unroll
    for (int i = 0; i < 4; ++i) {
        const float alpha = __ldg(params + 2 * i);
        const float beta  = __ldg(params + 2 * i + 1);
        float sb, cb;  sincosf(beta, &sb, &cb);
        const float sa = sinf(alpha);
        const float th = s[i] * (1.0f / 36.0f);
        float st, ct;  sincosf(th, &st, &ct);
        e[i] = cb * ct + sa * sb * st;
    }

    const float o0 = e[0];
    const float o1 = o0 * e[1];
    const float o2 = o1 * e[2];
    const float o3 = o2 * e[3];

    reinterpret_cast<float4*>(raw)[b] = make_float4(o0, o1, o2, o3);

    // ---- deterministic reduction of (sum, sumsq) in double ----
    double q[8];
    q[0] = (double)o0;  q[1] = (double)o1;  q[2] = (double)o2;  q[3] = (double)o3;
    q[4] = q[0] * q[0]; q[5] = q[1] * q[1]; q[6] = q[2] * q[2]; q[7] = q[3] * q[3];

    #pragma unroll
    for (int off = 16; off > 0; off >>= 1) {
        #pragma unroll
        for (int j = 0; j < 8; ++j)
            q[j] += __shfl_down_sync(0xffffffffu, q[j], off);
    }

    __shared__ double sw[BLK / 32][8];
    const int warp = threadIdx.x >> 5;
    const int lane = threadIdx.x & 31;
    if (lane == 0) {
        #pragma unroll
        for (int j = 0; j < 8; ++j) sw[warp][j] = q[j];
    }
    __syncthreads();

    // threads 0..7: quantity j, fixed-order sum over the 8 warps
    if (threadIdx.x < 8) {
        double t = 0.0;
        #pragma unroll
        for (int w = 0; w < BLK / 32; ++w) t += sw[w][threadIdx.x];
        g_partial[threadIdx.x][blockIdx.x] = t;
    }
}

__global__ void k_stats(const float* __restrict__ gamma,
                        const float* __restrict__ beta,
                        int nblk, float inv_batch)
{
    // 8 warps, one per quantity. Fixed-order serial + shfl reduce (deterministic).
    __shared__ double tot[8];
    const int warp = threadIdx.x >> 5;
    const int lane = threadIdx.x & 31;

    if (warp < 8) {
        double v = 0.0;
        for (int i = lane; i < nblk; i += 32) v += g_partial[warp][i];
        #pragma unroll
        for (int off = 16; off > 0; off >>= 1)
            v += __shfl_down_sync(0xffffffffu, v, off);
        if (lane == 0) tot[warp] = v;
    }
    __syncthreads();

    if (threadIdx.x < 4) {
        const int i = threadIdx.x;
        const double mean = tot[i] * (double)inv_batch;
        const double var  = tot[i + 4] * (double)inv_batch - mean * mean;
        const float invstd = rsqrtf((float)var + 1e-5f);
        const float sc = __ldg(gamma + i) * invstd;
        g_scale[i] = sc;
        g_shift[i] = __ldg(beta + i) - (float)mean * sc;
    }
}

__global__ __launch_bounds__(BLK)
void k_bn(float* __restrict__ out)
{
    const int b = blockIdx.x * BLK + threadIdx.x;
    float4 v = reinterpret_cast<float4*>(out)[b];
    v.x = v.x * g_scale[0] + g_shift[0];
    v.y = v.y * g_scale[1] + g_shift[1];
    v.z = v.z * g_scale[2] + g_shift[2];
    v.w = v.w * g_scale[3] + g_shift[3];
    reinterpret_cast<float4*>(out)[b] = v;
}

extern "C" void kernel_launch(void* const* d_in, const int* in_sizes, int n_in,
                              void* d_out, int out_size)
{
    const float* x      = (const float*)d_in[0];   // [B,1,24,24]
    const float* params = (const float*)d_in[1];   // [4,2]
    const float* gamma  = (const float*)d_in[2];   // [4]
    const float* beta   = (const float*)d_in[3];   // [4]
    float* out = (float*)d_out;                    // [B,4] float32

    const int B    = in_sizes[0] / 576;            // 65536
    const int nblk = B / BLK;                      // 256

    k_circuit<<<nblk, BLK>>>(x, params, out);
    k_stats<<<1, 256>>>(gamma, beta, nblk, 1.0f / (float)B);
    k_bn<<<nblk, BLK>>>(out);
}

// round 5
// speedup vs baseline: 1.4332x; 1.4332x over previous
#include <cuda_runtime.h>
#include <cstdint>

// ---------------------------------------------------------------------------
// QFCModel analytic collapse, round 2: 4 lanes per image for coalesced loads.
//
//   theta_i = mean of pixels p in [0,144) with (p%24)/6 == i
//   e_i     = cos(beta_i)*cos(theta_i) + sin(alpha_i)*sin(beta_i)*sin(theta_i)
//   out     = [e0, e0*e1, e0*e1*e2, e0*e1*e2*e3], then BatchNorm1d (train).
//
// Lane r of a 4-lane group reads float4 indices f = 4t + r, t = 0..8.
// Quadrant class c = f mod 6 is constant for fixed (t mod 3):
//   c: 0 -> all 4 floats in q0     1 -> x,y in q0; z,w in q1
//      2 -> all in q1              3 -> all in q2
//      4 -> x,y in q2; z,w in q3   5 -> all in q3
// ---------------------------------------------------------------------------

#define BLK 256
#define MAX_NBLK 2048

__device__ double g_partial[8][MAX_NBLK];  // [0..3]=sum(q), [4..7]=sumsq(q)
__device__ float  g_scale[4];
__device__ float  g_shift[4];

__global__ __launch_bounds__(BLK)
void k_circuit(const float* __restrict__ x,
               const float* __restrict__ params,
               float* __restrict__ raw)
{
    const int t    = blockIdx.x * BLK + threadIdx.x;   // 4*B threads total
    const int b    = t >> 2;                            // image
    const int r    = t & 3;                             // sub-lane within group
    const int lane = threadIdx.x & 31;

    // image base is 128B-aligned; group of 4 lanes reads 64B contiguous/iter
    const float4* xv = reinterpret_cast<const float4*>(x) + (size_t)b * 144 + r;

    // batch all 9 loads for max MLP
    float4 v[9];
    #pragma unroll
    for (int tt = 0; tt < 9; ++tt) v[tt] = __ldg(xv + 4 * tt);

    // phase accumulators: phase j = t mod 3 has constant class (4j + r) mod 6
    float xy0 = 0.f, xy1 = 0.f, xy2 = 0.f;
    float zw0 = 0.f, zw1 = 0.f, zw2 = 0.f;
    #pragma unroll
    for (int tt = 0; tt < 9; ++tt) {
        const float a = v[tt].x + v[tt].y;
        const float c = v[tt].z + v[tt].w;
        if (tt % 3 == 0)      { xy0 += a; zw0 += c; }
        else if (tt % 3 == 1) { xy1 += a; zw1 += c; }
        else                  { xy2 += a; zw2 += c; }
    }

    // scatter phases into quadrant sums (classes per r are compile-time here)
    float s0 = 0.f, s1 = 0.f, s2 = 0.f, s3 = 0.f;
    switch (r) {
    case 0:  // classes (0,4,2)
        s0 = xy0 + zw0; s2 = xy1; s3 = zw1; s1 = xy2 + zw2; break;
    case 1:  // classes (1,5,3)
        s0 = xy0; s1 = zw0; s3 = xy1 + zw1; s2 = xy2 + zw2; break;
    case 2:  // classes (2,0,4)
        s1 = xy0 + zw0; s0 = xy1 + zw1; s2 = xy2; s3 = zw2; break;
    default: // classes (3,1,5)
        s2 = xy0 + zw0; s0 = xy1; s1 = zw1; s3 = xy2 + zw2; break;
    }

    // reduce across the 4 lanes of the group
    #pragma unroll
    for (int off = 1; off <= 2; off <<= 1) {
        s0 += __shfl_xor_sync(0xffffffffu, s0, off);
        s1 += __shfl_xor_sync(0xffffffffu, s1, off);
        s2 += __shfl_xor_sync(0xffffffffu, s2, off);
        s3 += __shfl_xor_sync(0xffffffffu, s3, off);
    }

    // lane r handles quadrant r
    const float sA = (r & 2) ? s2 : s0;
    const float sB = (r & 2) ? s3 : s1;
    const float sr = (r & 1) ? sB : sA;

    const float alpha = __ldg(params + 2 * r);
    const float beta  = __ldg(params + 2 * r + 1);
    float sb, cb;  sincosf(beta, &sb, &cb);
    const float sa = sinf(alpha);
    const float th = sr * (1.0f / 36.0f);
    float st, ct;  sincosf(th, &st, &ct);
    const float e = cb * ct + sa * sb * st;

    // cumulative product across the group (same rounding order as reference)
    const int gbase = lane & ~3;
    const float e0 = __shfl_sync(0xffffffffu, e, gbase + 0);
    const float e1 = __shfl_sync(0xffffffffu, e, gbase + 1);
    const float e2 = __shfl_sync(0xffffffffu, e, gbase + 2);
    const float e3 = __shfl_sync(0xffffffffu, e, gbase + 3);
    float o = e0;
    o *= (r >= 1) ? e1 : 1.f;
    o *= (r >= 2) ? e2 : 1.f;
    o *= (r >= 3) ? e3 : 1.f;

    raw[t] = o;   // t == 4*b + r: fully coalesced

    // ---- deterministic BN partials (double) ----
    // lanes with equal (lane&3) hold the same quantity for 8 images in the warp
    double od = (double)o;
    double oq = od * od;
    #pragma unroll
    for (int off = 4; off <= 16; off <<= 1) {
        od += __shfl_xor_sync(0xffffffffu, od, off);
        oq += __shfl_xor_sync(0xffffffffu, oq, off);
    }

    __shared__ double sw[BLK / 32][4][2];
    const int warp = threadIdx.x >> 5;
    if (lane < 4) { sw[warp][lane][0] = od; sw[warp][lane][1] = oq; }
    __syncthreads();

    if (threadIdx.x < 8) {
        const int q     = threadIdx.x & 3;
        const int which = threadIdx.x >> 2;
        double tsum = 0.0;
        #pragma unroll
        for (int w = 0; w < BLK / 32; ++w) tsum += sw[w][q][which];
        // j = which*4 + q == threadIdx.x : [0..3]=sum, [4..7]=sumsq
        g_partial[threadIdx.x][blockIdx.x] = tsum;
    }
}

__global__ void k_stats(const float* __restrict__ gamma,
                        const float* __restrict__ beta,
                        int nblk, double inv_batch)
{
    __shared__ double tot[8];
    const int warp = threadIdx.x >> 5;
    const int lane = threadIdx.x & 31;

    if (warp < 8) {
        double v = 0.0;
        for (int i = lane; i < nblk; i += 32) v += g_partial[warp][i];
        #pragma unroll
        for (int off = 16; off > 0; off >>= 1)
            v += __shfl_xor_sync(0xffffffffu, v, off);
        if (lane == 0) tot[warp] = v;
    }
    __syncthreads();

    if (threadIdx.x < 4) {
        const int i = threadIdx.x;
        const double mean = tot[i] * inv_batch;
        const double var  = tot[i + 4] * inv_batch - mean * mean;
        const float invstd = rsqrtf((float)var + 1e-5f);
        const float sc = __ldg(gamma + i) * invstd;
        g_scale[i] = sc;
        g_shift[i] = __ldg(beta + i) - (float)mean * sc;
    }
}

__global__ __launch_bounds__(BLK)
void k_bn(float* __restrict__ out)
{
    const int b = blockIdx.x * BLK + threadIdx.x;
    float4 v = reinterpret_cast<float4*>(out)[b];
    v.x = v.x * g_scale[0] + g_shift[0];
    v.y = v.y * g_scale[1] + g_shift[1];
    v.z = v.z * g_scale[2] + g_shift[2];
    v.w = v.w * g_scale[3] + g_shift[3];
    reinterpret_cast<float4*>(out)[b] = v;
}

extern "C" void kernel_launch(void* const* d_in, const int* in_sizes, int n_in,
                              void* d_out, int out_size)
{
    const float* x      = (const float*)d_in[0];   // [B,1,24,24]
    const float* params = (const float*)d_in[1];   // [4,2]
    const float* gamma  = (const float*)d_in[2];   // [4]
    const float* beta   = (const float*)d_in[3];   // [4]
    float* out = (float*)d_out;                    // [B,4] float32

    const int B    = in_sizes[0] / 576;            // 65536
    const int nblk = (4 * B) / BLK;                // 1024 (64 images / block)

    k_circuit<<<nblk, BLK>>>(x, params, out);
    k_stats<<<1, 256>>>(gamma, beta, nblk, 1.0 / (double)B);
    k_bn<<<B / BLK, BLK>>>(out);
}